// round 2
// baseline (speedup 1.0000x reference)
#include <cuda_runtime.h>

#define N_ROWS 32768
#define D 64
#define K 1024
#define KC 256   // k-chunk resident in smem
#define TG 16    // k per accumulator group (8 packed f32x2 accumulators)

__device__ float d_en[K];          // fp32 ||e_k||^2, mul-then-add (no fma), like ref
__device__ float d_eT[K * D];      // codebook transposed [K][D]
__device__ int   d_idx[N_ROWS];
__device__ float d_lossAcc;
__device__ int   d_flagCnt;
__device__ int   d_flagList[N_ROWS];

typedef unsigned long long u64;

__device__ __forceinline__ u64 ffma2(u64 a, u64 b, u64 c) {
    u64 d;
    asm("fma.rn.f32x2 %0, %1, %2, %3;" : "=l"(d) : "l"(a), "l"(b), "l"(c));
    return d;
}
__device__ __forceinline__ u64 pack_dup(float x) {
    u64 p;
    asm("mov.b64 %0, {%1, %2};" : "=l"(p) : "f"(x), "f"(x));
    return p;
}
__device__ __forceinline__ void unpack2(u64 p, float& lo, float& hi) {
    asm("mov.b64 {%0, %1}, %2;" : "=f"(lo), "=f"(hi) : "l"(p));
}

// Kernel 0: codebook norms (mul-then-add fp32, sequential) + transpose; zero accs.
__global__ void prep_kernel(const float* __restrict__ emb) {
    int k = blockIdx.x * blockDim.x + threadIdx.x;
    if (k == 0) { d_lossAcc = 0.0f; d_flagCnt = 0; }
    if (k < K) {
        float s = 0.0f;
        #pragma unroll
        for (int dd = 0; dd < D; dd++) {
            float v = emb[dd * K + k];   // coalesced across lanes
            s = __fadd_rn(s, __fmul_rn(v, v));  // no fma contraction: match ref e*e then sum
            d_eT[k * D + dd] = v;
        }
        d_en[k] = s;
    }
}

// Kernel 1: fast fp32 argmin over (||e_k||^2 - 2 x.e_k); flags near-tie rows.
__global__ __launch_bounds__(256, 1)
void argmin_kernel(const float* __restrict__ x, const float* __restrict__ emb) {
    __shared__ __align__(16) float sE[D * KC];  // [d][kc]
    __shared__ __align__(16) float sC[KC];

    int row = blockIdx.x * 256 + threadIdx.x;

    float xr[D];
    const float4* xv = (const float4*)(x + row * D);
    #pragma unroll
    for (int i = 0; i < D / 4; i++) {
        float4 v = xv[i];
        xr[4*i] = v.x; xr[4*i+1] = v.y; xr[4*i+2] = v.z; xr[4*i+3] = v.w;
    }

    float best = 3.4e38f, best2 = 3.4e38f;
    int bidx = 0;

    for (int k0 = 0; k0 < K; k0 += KC) {
        __syncthreads();
        #pragma unroll
        for (int i = 0; i < 16; i++) {
            int f = threadIdx.x + i * 256;
            int dd = f >> 6;
            int j  = f & 63;
            float4 v = *(const float4*)(emb + dd * K + k0 + 4 * j);
            *(float4*)(sE + dd * KC + 4 * j) = v;
        }
        if (threadIdx.x < KC / 4) {
            float4 c = *(const float4*)(d_en + k0 + threadIdx.x * 4);
            *(float4*)(sC + threadIdx.x * 4) = c;
        }
        __syncthreads();

        for (int g = 0; g < KC / TG; g++) {
            u64 acc[TG / 2];
            #pragma unroll
            for (int t = 0; t < TG / 2; t++) acc[t] = 0ull;

            #pragma unroll
            for (int dd = 0; dd < D; dd++) {
                u64 xd = pack_dup(xr[dd]);
                const ulonglong2* ep = (const ulonglong2*)(sE + dd * KC + g * TG);
                #pragma unroll
                for (int t2 = 0; t2 < TG / 4; t2++) {
                    ulonglong2 e2 = ep[t2];
                    acc[2*t2]     = ffma2(xd, e2.x, acc[2*t2]);
                    acc[2*t2 + 1] = ffma2(xd, e2.y, acc[2*t2 + 1]);
                }
            }
            #pragma unroll
            for (int t = 0; t < TG / 2; t++) {
                float lo, hi;
                unpack2(acc[t], lo, hi);
                int kk = k0 + g * TG + 2 * t;
                float s0 = sC[g * TG + 2 * t]     - 2.0f * lo;
                float s1 = sC[g * TG + 2 * t + 1] - 2.0f * hi;
                if (s0 < best) { best2 = best; best = s0; bidx = kk; }
                else if (s0 < best2) { best2 = s0; }
                if (s1 < best) { best2 = best; best = s1; bidx = kk + 1; }
                else if (s1 < best2) { best2 = s1; }
            }
        }
    }
    d_idx[row] = bidx;
    if (best2 - best < 1e-4f) {                 // near-tie: needs exact ref-rounding resolve
        int p = atomicAdd(&d_flagCnt, 1);
        d_flagList[p] = row;
    }
}

// Kernel 2: exact resolve for flagged rows — emulate reference fp32 rounding:
// dist = fl32( fl32(xn + en_k) - fl32(2*sim) ), sim in fp64.
__global__ __launch_bounds__(256, 1)
void refine_kernel(const float* __restrict__ x) {
    __shared__ float sx[D];
    __shared__ float sxn;
    __shared__ float rv[256];
    __shared__ int   ri[256];
    int tid = threadIdx.x;

    int cnt = d_flagCnt;
    for (int i = blockIdx.x; i < cnt; i += gridDim.x) {
        int row = d_flagList[i];
        if (tid < D / 4) {
            float4 v = *(const float4*)(x + row * D + 4 * tid);
            sx[4*tid] = v.x; sx[4*tid+1] = v.y; sx[4*tid+2] = v.z; sx[4*tid+3] = v.w;
        }
        __syncthreads();
        if (tid == 0) {
            float a = 0.0f;
            for (int dd = 0; dd < D; dd++)
                a = __fadd_rn(a, __fmul_rn(sx[dd], sx[dd]));   // mul-then-add, sequential
            sxn = a;
        }
        __syncthreads();
        float xn = sxn;

        float bv = 3.4e38f; int bi = 0;
        #pragma unroll
        for (int t = 0; t < 4; t++) {
            int k = tid * 4 + t;
            double sim = 0.0;
            #pragma unroll
            for (int dd = 0; dd < D; dd++)
                sim = fma((double)sx[dd], (double)d_eT[k * D + dd], sim);
            float s2 = (float)(2.0 * sim);
            float t1 = __fadd_rn(xn, d_en[k]);
            float dist = __fsub_rn(t1, s2);
            if (dist < bv) { bv = dist; bi = k; }
        }
        rv[tid] = bv; ri[tid] = bi;
        __syncthreads();
        for (int off = 128; off > 0; off >>= 1) {
            if (tid < off) {
                float ov = rv[tid + off]; int oi = ri[tid + off];
                if (ov < rv[tid] || (ov == rv[tid] && oi < ri[tid])) {
                    rv[tid] = ov; ri[tid] = oi;
                }
            }
            __syncthreads();
        }
        if (tid == 0) d_idx[row] = ri[0];
        __syncthreads();
    }
}

// Kernel 3: gather + straight-through output + loss partial sums.
__global__ void out_kernel(const float* __restrict__ x, float* __restrict__ out) {
    int gid = blockIdx.x * blockDim.x + threadIdx.x;
    int r = gid >> 6, dd = gid & 63;
    int idx = d_idx[r];
    float xvl = x[gid];
    float q = d_eT[idx * D + dd];
    float diff = q - xvl;
    out[gid] = xvl + diff;
    float v = diff * diff;

    #pragma unroll
    for (int o = 16; o > 0; o >>= 1) v += __shfl_xor_sync(0xffffffff, v, o);
    __shared__ float ws[8];
    int wid = threadIdx.x >> 5, lid = threadIdx.x & 31;
    if (lid == 0) ws[wid] = v;
    __syncthreads();
    if (threadIdx.x == 0) {
        float s = 0.0f;
        #pragma unroll
        for (int i = 0; i < 8; i++) s += ws[i];
        atomicAdd(&d_lossAcc, s);
    }
}

// Kernel 4: loss = 1.25 * sum / (N*D)
__global__ void fin_kernel(float* __restrict__ out, int out_size) {
    out[out_size - 1] = 1.25f * d_lossAcc * (1.0f / (float)(N_ROWS * D));
}

extern "C" void kernel_launch(void* const* d_in, const int* in_sizes, int n_in,
                              void* d_out, int out_size) {
    const float* x   = (const float*)d_in[0];
    const float* emb = (const float*)d_in[1];
    float* out = (float*)d_out;

    prep_kernel<<<4, 256>>>(emb);
    argmin_kernel<<<N_ROWS / 256, 256>>>(x, emb);
    refine_kernel<<<32, 256>>>(x);
    out_kernel<<<(N_ROWS * D) / 256, 256>>>(x, out);
    fin_kernel<<<1, 1>>>(out, out_size);
}

// round 4
// speedup vs baseline: 1.0248x; 1.0248x over previous
#include <cuda_runtime.h>
#include <cuda_bf16.h>
#include <cstdint>

#define N_ROWS 32768
#define D 64
#define K 1024
#define KPAD 88            // padded k-extent (elements); row stride 176 B
#define TM 128             // rows per CTA
#define GAP_THRESH 3e-4f

__device__ float d_en[K];                         // fp32 ||e_k||^2 (mul-then-add, sequential)
__device__ float d_eT[K * D];                     // [k][d] fp32 for refine/gather
__device__ __align__(16) __nv_bfloat16 d_Bhi[K * KPAD];  // [k][KPAD] bf16 hi (+aug en_hi at 64)
__device__ __align__(16) __nv_bfloat16 d_Blo[K * KPAD];  // [k][KPAD] bf16 lo (+aug en_lo at 64)
__device__ int   d_idx[N_ROWS];
__device__ float d_lossAcc;
__device__ int   d_flagCnt;
__device__ int   d_flagList[N_ROWS];

// ---------------- helpers ----------------
__device__ __forceinline__ uint32_t smem_u32(const void* p) {
    uint32_t a;
    asm("{ .reg .u64 t; cvta.to.shared.u64 t, %1; cvt.u32.u64 %0, t; }" : "=r"(a) : "l"(p));
    return a;
}
__device__ __forceinline__ void ldm_x4(uint32_t* r, uint32_t addr) {
    asm volatile("ldmatrix.sync.aligned.m8n8.x4.shared.b16 {%0,%1,%2,%3}, [%4];"
        : "=r"(r[0]), "=r"(r[1]), "=r"(r[2]), "=r"(r[3]) : "r"(addr));
}
__device__ __forceinline__ void mma_bf16(float* d, const uint32_t* a, const uint32_t* b) {
    asm volatile("mma.sync.aligned.m16n8k16.row.col.f32.bf16.bf16.f32 "
        "{%0,%1,%2,%3}, {%4,%5,%6,%7}, {%8,%9}, {%0,%1,%2,%3};"
        : "+f"(d[0]), "+f"(d[1]), "+f"(d[2]), "+f"(d[3])
        : "r"(a[0]), "r"(a[1]), "r"(a[2]), "r"(a[3]), "r"(b[0]), "r"(b[1]));
}

// ---------------- Kernel 0: prep ----------------
__global__ void prep_kernel(const float* __restrict__ emb) {
    int k = blockIdx.x * blockDim.x + threadIdx.x;
    if (k == 0) { d_lossAcc = 0.0f; d_flagCnt = 0; }
    if (k < K) {
        float s = 0.0f;
        #pragma unroll
        for (int dd = 0; dd < D; dd++) {
            float v = emb[dd * K + k];                     // coalesced across lanes
            s = __fadd_rn(s, __fmul_rn(v, v));             // ref-style mul-then-add
            d_eT[k * D + dd] = v;
            __nv_bfloat16 h = __float2bfloat16(v);
            __nv_bfloat16 l = __float2bfloat16(v - __bfloat162float(h));
            d_Bhi[k * KPAD + dd] = h;
            d_Blo[k * KPAD + dd] = l;
        }
        d_en[k] = s;
        // augmentation column: dist = en + (-2x).e accumulates fully in the MMA
        __nv_bfloat16 eh = __float2bfloat16(s);
        __nv_bfloat16 el = __float2bfloat16(s - __bfloat162float(eh));
        d_Bhi[k * KPAD + 64] = eh;
        d_Blo[k * KPAD + 64] = el;
        for (int dd = 65; dd < KPAD; dd++) {
            d_Bhi[k * KPAD + dd] = __float2bfloat16(0.0f);
            d_Blo[k * KPAD + dd] = __float2bfloat16(0.0f);
        }
    }
}

// ---------------- Kernel 1: HMMA GEMM + fused argmin ----------------
// smem: A_hi[128][88]bf16, A_lo[128][88], B hi/lo double-buffered [64][88]
#define ROWB 176
#define S_AH  0
#define S_AL  22528
#define S_B   45056          // 4 planes of 11264: [buf][plane]
#define PLANE 11264
#define S_TOTAL 90112

__global__ __launch_bounds__(256, 2)
void gemm_argmin_kernel(const float* __restrict__ x) {
    extern __shared__ char smem[];
    uint32_t sb = smem_u32(smem);
    int tid = threadIdx.x;
    int lane = tid & 31, warp = tid >> 5;
    int m0 = warp * 16;
    int row0 = blockIdx.x * TM;

    // ---- A: load x rows, convert to bf16 hi/lo of (-2x), store padded ----
    #pragma unroll
    for (int i = 0; i < 8; i++) {
        int f = tid + i * 256;          // 2048 float4 = 128 rows x 16
        int row = f >> 4, j = f & 15;
        float4 v = *(const float4*)(x + (row0 + row) * D + 4 * j);
        float a0 = -2.0f * v.x, a1 = -2.0f * v.y, a2 = -2.0f * v.z, a3 = -2.0f * v.w;
        __nv_bfloat16 h0 = __float2bfloat16(a0), h1 = __float2bfloat16(a1);
        __nv_bfloat16 h2 = __float2bfloat16(a2), h3 = __float2bfloat16(a3);
        __nv_bfloat16 l0 = __float2bfloat16(a0 - __bfloat162float(h0));
        __nv_bfloat16 l1 = __float2bfloat16(a1 - __bfloat162float(h1));
        __nv_bfloat16 l2 = __float2bfloat16(a2 - __bfloat162float(h2));
        __nv_bfloat16 l3 = __float2bfloat16(a3 - __bfloat162float(h3));
        uint32_t off = (uint32_t)row * ROWB + j * 8;
        *(uint2*)(smem + S_AH + off) = make_uint2(
            (uint32_t)__bfloat16_as_ushort(h0) | ((uint32_t)__bfloat16_as_ushort(h1) << 16),
            (uint32_t)__bfloat16_as_ushort(h2) | ((uint32_t)__bfloat16_as_ushort(h3) << 16));
        *(uint2*)(smem + S_AL + off) = make_uint2(
            (uint32_t)__bfloat16_as_ushort(l0) | ((uint32_t)__bfloat16_as_ushort(l1) << 16),
            (uint32_t)__bfloat16_as_ushort(l2) | ((uint32_t)__bfloat16_as_ushort(l3) << 16));
    }
    // pad cols 64..87: A_hi aug=1 at 64, rest 0; A_lo all 0
    if (tid < 128) {
        uint32_t base = (uint32_t)tid * ROWB + 128;     // byte offset of col 64
        *(uint4*)(smem + S_AH + base)      = make_uint4(0x3F80u, 0u, 0u, 0u);
        *(uint4*)(smem + S_AH + base + 16) = make_uint4(0u, 0u, 0u, 0u);
        *(uint4*)(smem + S_AH + base + 32) = make_uint4(0u, 0u, 0u, 0u);
        *(uint4*)(smem + S_AL + base)      = make_uint4(0u, 0u, 0u, 0u);
        *(uint4*)(smem + S_AL + base + 16) = make_uint4(0u, 0u, 0u, 0u);
        *(uint4*)(smem + S_AL + base + 32) = make_uint4(0u, 0u, 0u, 0u);
    }

    // ---- B chunk loader: flat copy (same [n][KPAD] layout in gmem & smem) ----
    auto loadB = [&](int chunk) {
        uint32_t dst = S_B + (uint32_t)(chunk & 1) * (2 * PLANE);
        const uint4* gh = (const uint4*)d_Bhi + chunk * 704;   // 64*88/8
        const uint4* gl = (const uint4*)d_Blo + chunk * 704;
        #pragma unroll
        for (int i = 0; i < 3; i++) {
            int u = tid + i * 256;
            if (u < 704) {
                *(uint4*)(smem + dst + 16 * u) = gh[u];
                *(uint4*)(smem + dst + PLANE + 16 * u) = gl[u];
            }
        }
    };

    loadB(0);
    __syncthreads();

    // ---- per-lane ldmatrix addresses ----
    int r = lane & 7, q = lane >> 3;
    uint32_t aAddr = sb + (uint32_t)(m0 + r + ((q & 1) << 3)) * ROWB + ((q >> 1) << 4);
    uint32_t aAddrLo = aAddr + S_AL;   // S_AH == 0
    uint32_t bOff = (uint32_t)(r + ((q >> 1) << 3)) * ROWB + ((q & 1) << 4);

    // persistent A_hi fragments (5 k-steps)
    uint32_t ah[5][4];
    #pragma unroll
    for (int k = 0; k < 5; k++) ldm_x4(ah[k], aAddr + k * 32);

    float bA = 3.4e38f, b2A = 3.4e38f, bB = 3.4e38f, b2B = 3.4e38f;
    int iA = 0, iB = 0;

    #pragma unroll 1
    for (int c = 0; c < 16; c++) {
        if (c < 15) loadB(c + 1);     // prefetch into other buffer

        uint32_t bh_base = sb + S_B + (uint32_t)(c & 1) * (2 * PLANE) + bOff;
        uint32_t bl_base = bh_base + PLANE;

        float acc[8][4];
        #pragma unroll
        for (int nb = 0; nb < 8; nb++)
            #pragma unroll
            for (int j = 0; j < 4; j++) acc[nb][j] = 0.0f;

        #pragma unroll
        for (int k = 0; k < 5; k++) {
            uint32_t al4[4];
            ldm_x4(al4, aAddrLo + k * 32);
            uint32_t bh[4][4];
            #pragma unroll
            for (int t = 0; t < 4; t++) ldm_x4(bh[t], bh_base + t * (16 * ROWB) + k * 32);
            #pragma unroll
            for (int t = 0; t < 4; t++) {
                mma_bf16(acc[2*t],   ah[k], bh[t]);
                mma_bf16(acc[2*t+1], ah[k], bh[t] + 2);
            }
            #pragma unroll
            for (int t = 0; t < 4; t++) {
                mma_bf16(acc[2*t],   al4, bh[t]);
                mma_bf16(acc[2*t+1], al4, bh[t] + 2);
            }
            uint32_t bl[4][4];
            #pragma unroll
            for (int t = 0; t < 4; t++) ldm_x4(bl[t], bl_base + t * (16 * ROWB) + k * 32);
            #pragma unroll
            for (int t = 0; t < 4; t++) {
                mma_bf16(acc[2*t],   ah[k], bl[t]);
                mma_bf16(acc[2*t+1], ah[k], bl[t] + 2);
            }
        }

        // epilogue: acc == dist = en - 2 x.e
        int kbase = c * 64 + 2 * (lane & 3);
        #pragma unroll
        for (int nb = 0; nb < 8; nb++) {
            #pragma unroll
            for (int j = 0; j < 4; j++) {
                float v = acc[nb][j];
                int kidx = kbase + nb * 8 + (j & 1);
                if (j < 2) {
                    if (v < bA) { b2A = bA; bA = v; iA = kidx; } else b2A = fminf(b2A, v);
                } else {
                    if (v < bB) { b2B = bB; bB = v; iB = kidx; } else b2B = fminf(b2B, v);
                }
            }
        }
        __syncthreads();   // compute done on buf c, loads into buf c+1 complete
    }

    // ---- merge across the 4 lanes sharing each row ----
    #pragma unroll
    for (int off = 1; off <= 2; off <<= 1) {
        float ov = __shfl_xor_sync(0xffffffff, bA, off);
        float ov2 = __shfl_xor_sync(0xffffffff, b2A, off);
        int   oi = __shfl_xor_sync(0xffffffff, iA, off);
        if (ov < bA) { b2A = fminf(bA, ov2); bA = ov; iA = oi; } else b2A = fminf(b2A, ov);
        ov = __shfl_xor_sync(0xffffffff, bB, off);
        ov2 = __shfl_xor_sync(0xffffffff, b2B, off);
        oi = __shfl_xor_sync(0xffffffff, iB, off);
        if (ov < bB) { b2B = fminf(bB, ov2); bB = ov; iB = oi; } else b2B = fminf(b2B, ov);
    }
    if ((lane & 3) == 0) {
        int rowA = row0 + m0 + (lane >> 2);
        d_idx[rowA] = iA;
        if (b2A - bA < GAP_THRESH) { int p = atomicAdd(&d_flagCnt, 1); d_flagList[p] = rowA; }
        int rowB = rowA + 8;
        d_idx[rowB] = iB;
        if (b2B - bB < GAP_THRESH) { int p = atomicAdd(&d_flagCnt, 1); d_flagList[p] = rowB; }
    }
}

// ---------------- Kernel 2: exact fp64 resolve (validated in R2) ----------------
__global__ __launch_bounds__(256, 1)
void refine_kernel(const float* __restrict__ x) {
    __shared__ float sx[D];
    __shared__ float sxn;
    __shared__ float rv[256];
    __shared__ int   ri[256];
    int tid = threadIdx.x;

    int cnt = d_flagCnt;
    for (int i = blockIdx.x; i < cnt; i += gridDim.x) {
        int row = d_flagList[i];
        if (tid < D / 4) {
            float4 v = *(const float4*)(x + row * D + 4 * tid);
            sx[4*tid] = v.x; sx[4*tid+1] = v.y; sx[4*tid+2] = v.z; sx[4*tid+3] = v.w;
        }
        __syncthreads();
        if (tid == 0) {
            float a = 0.0f;
            for (int dd = 0; dd < D; dd++)
                a = __fadd_rn(a, __fmul_rn(sx[dd], sx[dd]));
            sxn = a;
        }
        __syncthreads();
        float xn = sxn;

        float bv = 3.4e38f; int bi = 0;
        #pragma unroll
        for (int t = 0; t < 4; t++) {
            int k = tid * 4 + t;
            double sim = 0.0;
            #pragma unroll
            for (int dd = 0; dd < D; dd++)
                sim = fma((double)sx[dd], (double)d_eT[k * D + dd], sim);
            float s2 = (float)(2.0 * sim);
            float t1 = __fadd_rn(xn, d_en[k]);
            float dist = __fsub_rn(t1, s2);
            if (dist < bv) { bv = dist; bi = k; }
        }
        rv[tid] = bv; ri[tid] = bi;
        __syncthreads();
        for (int off = 128; off > 0; off >>= 1) {
            if (tid < off) {
                float ov = rv[tid + off]; int oi = ri[tid + off];
                if (ov < rv[tid] || (ov == rv[tid] && oi < ri[tid])) {
                    rv[tid] = ov; ri[tid] = oi;
                }
            }
            __syncthreads();
        }
        if (tid == 0) d_idx[row] = ri[0];
        __syncthreads();
    }
}

// ---------------- Kernel 3: gather + straight-through + loss ----------------
__global__ void out_kernel(const float* __restrict__ x, float* __restrict__ out) {
    int t = blockIdx.x * blockDim.x + threadIdx.x;   // float4 index
    int r = t >> 4, j = t & 15;
    int idx = d_idx[r];
    float4 xv = ((const float4*)x)[t];
    float4 qv = *(const float4*)(d_eT + idx * D + 4 * j);
    float dx = qv.x - xv.x, dy = qv.y - xv.y, dz = qv.z - xv.z, dw = qv.w - xv.w;
    ((float4*)out)[t] = make_float4(xv.x + dx, xv.y + dy, xv.z + dz, xv.w + dw);
    float v = dx * dx + dy * dy + dz * dz + dw * dw;

    #pragma unroll
    for (int off = 16; off > 0; off >>= 1) v += __shfl_xor_sync(0xffffffff, v, off);
    __shared__ float ws[8];
    int wid = threadIdx.x >> 5, lid = threadIdx.x & 31;
    if (lid == 0) ws[wid] = v;
    __syncthreads();
    if (threadIdx.x == 0) {
        float s = 0.0f;
        #pragma unroll
        for (int i = 0; i < 8; i++) s += ws[i];
        atomicAdd(&d_lossAcc, s);
    }
}

// ---------------- Kernel 4: finalize loss ----------------
__global__ void fin_kernel(float* __restrict__ out, int out_size) {
    out[out_size - 1] = 1.25f * d_lossAcc * (1.0f / (float)(N_ROWS * D));
}

extern "C" void kernel_launch(void* const* d_in, const int* in_sizes, int n_in,
                              void* d_out, int out_size) {
    const float* x   = (const float*)d_in[0];
    const float* emb = (const float*)d_in[1];
    float* out = (float*)d_out;

    cudaFuncSetAttribute(gemm_argmin_kernel,
                         cudaFuncAttributeMaxDynamicSharedMemorySize, S_TOTAL);

    prep_kernel<<<4, 256>>>(emb);
    gemm_argmin_kernel<<<N_ROWS / TM, 256, S_TOTAL>>>(x);
    refine_kernel<<<32, 256>>>(x);
    out_kernel<<<(N_ROWS * D / 4) / 256, 256>>>(x, out);
    fin_kernel<<<1, 1>>>(out, out_size);
}